// round 15
// baseline (speedup 1.0000x reference)
#include <cuda_runtime.h>
#include <cuda_fp16.h>
#include <mma.h>

using namespace nvcuda;

#define NMAX 100000
#define FIN  512
#define HID  16
#define XPAD 36
#define WPAD 20

// ---------------- scratch (zero-initialized at module load) ----------------
__device__ float  d_deg  [NMAX];         // degree excl self-loop (re-zeroed)
__device__ float  d_dinv [NMAX];         // (deg+1)^-1/2
__device__ float  d_h1f  [NMAX * HID];   // raw fp32 h1 from gemm
__device__ __half d_h1h  [NMAX * HID];   // fp16 pre-scaled messages (32B/row)
__device__ __half d_acc1 [NMAX * HID];   // fp16 layer-1 accumulator
__device__ float  d_gp   [NMAX];         // g * dinv[row]
__device__ float  d_acc2 [NMAX];         // layer-2 accumulator (fp32)

__device__ __forceinline__ unsigned smem_u32(const void* p) {
    unsigned r;
    asm("{ .reg .u64 t; cvta.to.shared.u64 t, %1; cvt.u32.u64 %0, t; }"
        : "=r"(r) : "l"(p));
    return r;
}

// prefetch one 256-row x 32-col x tile into smem via cp.async (XPAD stride).
// 128 gemm threads x 16 float4.
__device__ __forceinline__ void tile_prefetch(const float* __restrict__ x,
                                              unsigned bufbase, int rbase,
                                              int kt, int tid, int N) {
    #pragma unroll
    for (int i = 0; i < 16; i++) {
        int fid = tid + i * 128;
        int r = fid >> 3, c4 = fid & 7;
        int gr = rbase + r;
        if (gr < N) {
            const float* g = x + (size_t)gr * FIN + kt * 32 + c4 * 4;
            unsigned d = bufbase + (unsigned)(r * (XPAD * 4) + c4 * 16);
            asm volatile("cp.async.cg.shared.global [%0], [%1], 16;"
                         :: "r"(d), "l"(g));
        }
    }
    asm volatile("cp.async.commit_group;");
}

// Fused: warps 0-3 = tf32 WMMA GEMM (64 rows/warp, 256 rows/block),
//        warps 4-7 = degree histogram (barrier-free, chains pipeline freely).
__global__ void __launch_bounds__(256, 2) k_gemmdeg(const float* __restrict__ x,
                                                    const float* __restrict__ W1,
                                                    const int* __restrict__ dst,
                                                    int N, int E) {
    extern __shared__ float sm[];
    float* Ws = sm;                          // 512 x WPAD (40KB) tf32
    float* xs = sm + FIN * WPAD;             // 2 x 256 x XPAD (72KB)
    int tid = threadIdx.x;

    if (tid >= 128) {                        // ---- degree warps ----
        int dt = tid - 128;
        long long start = (long long)blockIdx.x * E / gridDim.x;
        long long stop  = (long long)(blockIdx.x + 1) * E / gridDim.x;
        for (long long e = start + dt; e < stop; e += 128)
            atomicAdd(&d_deg[dst[e]], 1.0f);
        return;
    }

    {   // stage W1, tf32-converted
        const float4* W4 = (const float4*)W1;
        #pragma unroll
        for (int i = 0; i < 16; i++) {
            int f = tid + i * 128;
            int row = f >> 2, c4 = f & 3;
            float4 v = W4[f];
            v.x = wmma::__float_to_tf32(v.x);
            v.y = wmma::__float_to_tf32(v.y);
            v.z = wmma::__float_to_tf32(v.z);
            v.w = wmma::__float_to_tf32(v.w);
            *(float4*)(Ws + row * WPAD + c4 * 4) = v;
        }
    }

    int warp = tid >> 5;                     // 0..3
    int wrow = warp * 64;
    int rbase = blockIdx.x * 256;
    unsigned buf0 = smem_u32(xs);

    wmma::fragment<wmma::accumulator, 16, 16, 8, float> c[4];
    #pragma unroll
    for (int t = 0; t < 4; t++) wmma::fill_fragment(c[t], 0.0f);

    tile_prefetch(x, buf0, rbase, 0, tid, N);

    #pragma unroll 1
    for (int kt = 0; kt < 16; kt++) {
        if (kt < 15) {
            tile_prefetch(x, buf0 + ((kt + 1) & 1) * (256 * XPAD * 4),
                          rbase, kt + 1, tid, N);
            asm volatile("cp.async.wait_group 1;");
        } else {
            asm volatile("cp.async.wait_group 0;");
        }
        asm volatile("bar.sync 1, 128;");    // gemm warps only

        const float* xb = xs + (kt & 1) * (256 * XPAD);
        #pragma unroll
        for (int kk = 0; kk < 4; kk++) {
            wmma::fragment<wmma::matrix_b, 16, 16, 8, wmma::precision::tf32,
                           wmma::row_major> b;
            wmma::load_matrix_sync(b, Ws + (kt * 32 + kk * 8) * WPAD, WPAD);
            #pragma unroll
            for (int t = 0; t < 4; t++) {
                wmma::fragment<wmma::matrix_a, 16, 16, 8, wmma::precision::tf32,
                               wmma::row_major> a;
                wmma::load_matrix_sync(a, xb + (wrow + t * 16) * XPAD + kk * 8,
                                       XPAD);
                #pragma unroll
                for (int i = 0; i < a.num_elements; i++)
                    a.x[i] = wmma::__float_to_tf32(a.x[i]);
                wmma::mma_sync(c[t], a, b, c[t]);
            }
        }
        asm volatile("bar.sync 1, 128;");
    }

    #pragma unroll
    for (int t = 0; t < 4; t++) {
        int r0 = rbase + wrow + t * 16;
        if (r0 < N)
            wmma::store_matrix_sync(d_h1f + (size_t)r0 * HID, c[t], HID,
                                    wmma::mem_row_major);
    }
}

// dinv; h1h = half(h1 * dinv); acc1 = h1h (self init); deg re-zeroed.
__global__ void k_scaledinv(int N4) {
    int t = blockIdx.x * blockDim.x + threadIdx.x;
    if (t >= N4) return;
    int row = t >> 2, q = t & 3;
    float dv = rsqrtf(d_deg[row] + 1.0f);
    if (q == 0) {
        d_dinv[row] = dv;
        d_deg[row]  = 0.0f;
    }
    float4 v = ((const float4*)d_h1f)[t];
    __half2 h0 = __floats2half2_rn(v.x * dv, v.y * dv);
    __half2 h1 = __floats2half2_rn(v.z * dv, v.w * dv);
    uint2 u = make_uint2(*(unsigned*)&h0, *(unsigned*)&h1);
    *(uint2*)(d_h1h  + (size_t)row * HID + q * 4) = u;
    *(uint2*)(d_acc1 + (size_t)row * HID + q * 4) = u;
}

// Layer-1 edge pass: acc1[dst] += h1h[src], fp16. 2 lanes/edge, red.v4.f16x2.
__global__ void k_edge1(const int* __restrict__ ei, int E) {
    int t = blockIdx.x * blockDim.x + threadIdx.x;
    int e = t >> 1, p = t & 1;
    if (e >= E) return;
    int s = ei[e];
    int d = ei[E + e];
    uint4 v = __ldg((const uint4*)(d_h1h + (size_t)s * HID + p * 8));
    __half* op = d_acc1 + (size_t)d * HID + p * 8;
    asm volatile("red.global.add.noftz.v4.f16x2 [%0],{%1,%2,%3,%4};"
                 :: "l"(op), "r"(v.x), "r"(v.y), "r"(v.z), "r"(v.w) : "memory");
}

// Per-node: h = relu(dinv*acc1 + b1); g = h.W2; gp = g*dinv; acc2 init.
__global__ void k_layer2(const float* __restrict__ b1,
                         const float* __restrict__ W2, int N) {
    int i = blockIdx.x * blockDim.x + threadIdx.x;
    if (i >= N) return;
    float dv = d_dinv[i];
    const uint4* ap = (const uint4*)(d_acc1 + (size_t)i * HID);
    float g = 0.f;
    #pragma unroll
    for (int q = 0; q < 2; q++) {
        uint4 u = ap[q];
        float2 f0 = __half22float2(*(__half2*)&u.x);
        float2 f1 = __half22float2(*(__half2*)&u.y);
        float2 f2 = __half22float2(*(__half2*)&u.z);
        float2 f3 = __half22float2(*(__half2*)&u.w);
        float4 b0 = __ldg(&((const float4*)b1)[q * 2]);
        float4 b4 = __ldg(&((const float4*)b1)[q * 2 + 1]);
        float4 w0 = __ldg(&((const float4*)W2)[q * 2]);
        float4 w4 = __ldg(&((const float4*)W2)[q * 2 + 1]);
        g += fmaxf(fmaf(dv, f0.x, b0.x), 0.f) * w0.x;
        g += fmaxf(fmaf(dv, f0.y, b0.y), 0.f) * w0.y;
        g += fmaxf(fmaf(dv, f1.x, b0.z), 0.f) * w0.z;
        g += fmaxf(fmaf(dv, f1.y, b0.w), 0.f) * w0.w;
        g += fmaxf(fmaf(dv, f2.x, b4.x), 0.f) * w4.x;
        g += fmaxf(fmaf(dv, f2.y, b4.y), 0.f) * w4.y;
        g += fmaxf(fmaf(dv, f3.x, b4.z), 0.f) * w4.z;
        g += fmaxf(fmaf(dv, f3.y, b4.w), 0.f) * w4.w;
    }
    float gp = g * dv;
    d_gp[i]   = gp;
    d_acc2[i] = gp;   // self-loop term
}

// Layer-2 edge pass: acc2[dst] += gp[src]. 4 edges/thread, MLP=4.
__global__ void k_edge2(const int* __restrict__ ei, int E) {
    int t = blockIdx.x * blockDim.x + threadIdx.x;
    int e4 = t * 4;
    if (e4 + 3 < E) {
        int4 s = __ldg((const int4*)(ei + e4));
        int4 d = __ldg((const int4*)(ei + E + e4));
        float g0 = __ldg(&d_gp[s.x]);
        float g1 = __ldg(&d_gp[s.y]);
        float g2 = __ldg(&d_gp[s.z]);
        float g3 = __ldg(&d_gp[s.w]);
        atomicAdd(&d_acc2[d.x], g0);
        atomicAdd(&d_acc2[d.y], g1);
        atomicAdd(&d_acc2[d.z], g2);
        atomicAdd(&d_acc2[d.w], g3);
    } else {
        for (int e = e4; e < E; e++)
            atomicAdd(&d_acc2[ei[E + e]], __ldg(&d_gp[ei[e]]));
    }
}

__global__ void k_sig(const float* __restrict__ b2, float* __restrict__ out, int N) {
    int i = blockIdx.x * blockDim.x + threadIdx.x;
    if (i >= N) return;
    float z = fmaf(d_dinv[i], d_acc2[i], __ldg(&b2[0]));
    out[i] = 1.f / (1.f + __expf(-z));
}

// ---------------- launch (single stream, 6 kernels) ----------------
extern "C" void kernel_launch(void* const* d_in, const int* in_sizes, int n_in,
                              void* d_out, int out_size) {
    const float* x  = (const float*)d_in[0];
    const float* W1 = (const float*)d_in[1];
    const float* b1 = (const float*)d_in[2];
    const float* W2 = (const float*)d_in[3];
    const float* b2 = (const float*)d_in[4];
    const int*   ei = (const int*)d_in[5];

    int N = in_sizes[0] / FIN;     // 100000
    int E = in_sizes[5] / 2;       // 3200000

    const int SMEM_BYTES = (FIN * WPAD + 2 * 256 * XPAD) * (int)sizeof(float);
    static bool inited = false;
    if (!inited) {
        cudaFuncSetAttribute(k_gemmdeg, cudaFuncAttributeMaxDynamicSharedMemorySize,
                             SMEM_BYTES);
        inited = true;
    }

    int nb = (N + 255) / 256;      // 391 blocks
    long long t1 = 2LL * E;

    k_gemmdeg  <<<nb, 256, SMEM_BYTES>>>(x, W1, ei + E, N, E);
    k_scaledinv<<<(N * 4 + 255) / 256, 256>>>(N * 4);
    k_edge1    <<<(unsigned)((t1 + 255) / 256), 256>>>(ei, E);
    k_layer2   <<<(N + 255) / 256, 256>>>(b1, W2, N);
    k_edge2    <<<((E / 4) + 255) / 256, 256>>>(ei, E);
    k_sig      <<<(N + 255) / 256, 256>>>(b2, (float*)d_out, N);
}

// round 16
// speedup vs baseline: 1.1280x; 1.1280x over previous
#include <cuda_runtime.h>
#include <cuda_fp16.h>
#include <mma.h>

using namespace nvcuda;

#define NMAX 100000
#define FIN  512
#define HID  16
#define XPAD 36
#define WPAD 20

// ---------------- scratch (zero-initialized at module load) ----------------
__device__ float  d_deg  [NMAX];         // degree excl self-loop (re-zeroed)
__device__ float  d_dinv [NMAX];         // (deg+1)^-1/2
__device__ float  d_h1f  [NMAX * HID];   // raw fp32 h1 from gemm
__device__ __half d_h1h  [NMAX * HID];   // fp16 pre-scaled messages (32B/row)
__device__ __half d_acc1 [NMAX * HID];   // fp16 layer-1 accumulator
__device__ float  d_gp   [NMAX];         // g * dinv[row]
__device__ float  d_acc2 [NMAX];         // layer-2 accumulator (fp32)

__device__ __forceinline__ unsigned smem_u32(const void* p) {
    unsigned r;
    asm("{ .reg .u64 t; cvta.to.shared.u64 t, %1; cvt.u32.u64 %0, t; }"
        : "=r"(r) : "l"(p));
    return r;
}

// prefetch one 256-row x 32-col x tile into smem via cp.async (XPAD stride).
// 256 gemm threads x 8 float4.
__device__ __forceinline__ void tile_prefetch(const float* __restrict__ x,
                                              unsigned bufbase, int rbase,
                                              int kt, int tid, int N) {
    #pragma unroll
    for (int i = 0; i < 8; i++) {
        int fid = tid + i * 256;
        int r = fid >> 3, c4 = fid & 7;
        int gr = rbase + r;
        if (gr < N) {
            const float* g = x + (size_t)gr * FIN + kt * 32 + c4 * 4;
            unsigned d = bufbase + (unsigned)(r * (XPAD * 4) + c4 * 16);
            asm volatile("cp.async.cg.shared.global [%0], [%1], 16;"
                         :: "r"(d), "l"(g));
        }
    }
    asm volatile("cp.async.commit_group;");
}

// Fused: warps 0-7 = tf32 WMMA GEMM (32 rows/warp, 256 rows/block),
//        warps 8-11 = degree histogram (barrier-free, pipelines freely).
__global__ void __launch_bounds__(384, 2) k_gemmdeg(const float* __restrict__ x,
                                                    const float* __restrict__ W1,
                                                    const int* __restrict__ dst,
                                                    int N, int E) {
    extern __shared__ float sm[];
    float* Ws = sm;                          // 512 x WPAD (40KB) tf32
    float* xs = sm + FIN * WPAD;             // 2 x 256 x XPAD (72KB)
    int tid = threadIdx.x;

    if (tid >= 256) {                        // ---- degree warps ----
        int dt = tid - 256;                  // 0..127
        long long start = (long long)blockIdx.x * E / gridDim.x;
        long long stop  = (long long)(blockIdx.x + 1) * E / gridDim.x;
        for (long long e = start + dt; e < stop; e += 128)
            atomicAdd(&d_deg[dst[e]], 1.0f);
        return;
    }

    {   // stage W1, tf32-converted: 8 float4/thread
        const float4* W4 = (const float4*)W1;
        #pragma unroll
        for (int i = 0; i < 8; i++) {
            int f = tid + i * 256;
            int row = f >> 2, c4 = f & 3;
            float4 v = W4[f];
            v.x = wmma::__float_to_tf32(v.x);
            v.y = wmma::__float_to_tf32(v.y);
            v.z = wmma::__float_to_tf32(v.z);
            v.w = wmma::__float_to_tf32(v.w);
            *(float4*)(Ws + row * WPAD + c4 * 4) = v;
        }
    }

    int warp = tid >> 5;                     // 0..7
    int wrow = warp * 32;
    int rbase = blockIdx.x * 256;
    unsigned buf0 = smem_u32(xs);

    wmma::fragment<wmma::accumulator, 16, 16, 8, float> c[2];
    wmma::fill_fragment(c[0], 0.0f);
    wmma::fill_fragment(c[1], 0.0f);

    tile_prefetch(x, buf0, rbase, 0, tid, N);

    #pragma unroll 1
    for (int kt = 0; kt < 16; kt++) {
        if (kt < 15) {
            tile_prefetch(x, buf0 + ((kt + 1) & 1) * (256 * XPAD * 4),
                          rbase, kt + 1, tid, N);
            asm volatile("cp.async.wait_group 1;");
        } else {
            asm volatile("cp.async.wait_group 0;");
        }
        asm volatile("bar.sync 1, 256;");    // gemm warps only

        const float* xb = xs + (kt & 1) * (256 * XPAD);
        #pragma unroll
        for (int kk = 0; kk < 4; kk++) {
            wmma::fragment<wmma::matrix_b, 16, 16, 8, wmma::precision::tf32,
                           wmma::row_major> b;
            wmma::load_matrix_sync(b, Ws + (kt * 32 + kk * 8) * WPAD, WPAD);
            #pragma unroll
            for (int t = 0; t < 2; t++) {
                wmma::fragment<wmma::matrix_a, 16, 16, 8, wmma::precision::tf32,
                               wmma::row_major> a;
                wmma::load_matrix_sync(a, xb + (wrow + t * 16) * XPAD + kk * 8,
                                       XPAD);
                #pragma unroll
                for (int i = 0; i < a.num_elements; i++)
                    a.x[i] = wmma::__float_to_tf32(a.x[i]);
                wmma::mma_sync(c[t], a, b, c[t]);
            }
        }
        asm volatile("bar.sync 1, 256;");
    }

    #pragma unroll
    for (int t = 0; t < 2; t++) {
        int r0 = rbase + wrow + t * 16;
        if (r0 < N)
            wmma::store_matrix_sync(d_h1f + (size_t)r0 * HID, c[t], HID,
                                    wmma::mem_row_major);
    }
}

// dinv; h1h = half(h1 * dinv); acc1 = h1h (self init); deg re-zeroed.
__global__ void k_scaledinv(int N4) {
    int t = blockIdx.x * blockDim.x + threadIdx.x;
    if (t >= N4) return;
    int row = t >> 2, q = t & 3;
    float dv = rsqrtf(d_deg[row] + 1.0f);
    if (q == 0) {
        d_dinv[row] = dv;
        d_deg[row]  = 0.0f;
    }
    float4 v = ((const float4*)d_h1f)[t];
    __half2 h0 = __floats2half2_rn(v.x * dv, v.y * dv);
    __half2 h1 = __floats2half2_rn(v.z * dv, v.w * dv);
    uint2 u = make_uint2(*(unsigned*)&h0, *(unsigned*)&h1);
    *(uint2*)(d_h1h  + (size_t)row * HID + q * 4) = u;
    *(uint2*)(d_acc1 + (size_t)row * HID + q * 4) = u;
}

// Layer-1 edge pass: acc1[dst] += h1h[src], fp16. 2 lanes/edge, red.v4.f16x2.
__global__ void k_edge1(const int* __restrict__ ei, int E) {
    int t = blockIdx.x * blockDim.x + threadIdx.x;
    int e = t >> 1, p = t & 1;
    if (e >= E) return;
    int s = ei[e];
    int d = ei[E + e];
    uint4 v = __ldg((const uint4*)(d_h1h + (size_t)s * HID + p * 8));
    __half* op = d_acc1 + (size_t)d * HID + p * 8;
    asm volatile("red.global.add.noftz.v4.f16x2 [%0],{%1,%2,%3,%4};"
                 :: "l"(op), "r"(v.x), "r"(v.y), "r"(v.z), "r"(v.w) : "memory");
}

// Per-node: h = relu(dinv*acc1 + b1); g = h.W2; gp = g*dinv; acc2 init.
__global__ void k_layer2(const float* __restrict__ b1,
                         const float* __restrict__ W2, int N) {
    int i = blockIdx.x * blockDim.x + threadIdx.x;
    if (i >= N) return;
    float dv = d_dinv[i];
    const uint4* ap = (const uint4*)(d_acc1 + (size_t)i * HID);
    float g = 0.f;
    #pragma unroll
    for (int q = 0; q < 2; q++) {
        uint4 u = ap[q];
        float2 f0 = __half22float2(*(__half2*)&u.x);
        float2 f1 = __half22float2(*(__half2*)&u.y);
        float2 f2 = __half22float2(*(__half2*)&u.z);
        float2 f3 = __half22float2(*(__half2*)&u.w);
        float4 b0 = __ldg(&((const float4*)b1)[q * 2]);
        float4 b4 = __ldg(&((const float4*)b1)[q * 2 + 1]);
        float4 w0 = __ldg(&((const float4*)W2)[q * 2]);
        float4 w4 = __ldg(&((const float4*)W2)[q * 2 + 1]);
        g += fmaxf(fmaf(dv, f0.x, b0.x), 0.f) * w0.x;
        g += fmaxf(fmaf(dv, f0.y, b0.y), 0.f) * w0.y;
        g += fmaxf(fmaf(dv, f1.x, b0.z), 0.f) * w0.z;
        g += fmaxf(fmaf(dv, f1.y, b0.w), 0.f) * w0.w;
        g += fmaxf(fmaf(dv, f2.x, b4.x), 0.f) * w4.x;
        g += fmaxf(fmaf(dv, f2.y, b4.y), 0.f) * w4.y;
        g += fmaxf(fmaf(dv, f3.x, b4.z), 0.f) * w4.z;
        g += fmaxf(fmaf(dv, f3.y, b4.w), 0.f) * w4.w;
    }
    float gp = g * dv;
    d_gp[i]   = gp;
    d_acc2[i] = gp;   // self-loop term
}

// Layer-2 edge pass: acc2[dst] += gp[src] (scalar, 1 edge/thread — best form).
__global__ void k_edge2(const int* __restrict__ ei, int E) {
    int e = blockIdx.x * blockDim.x + threadIdx.x;
    if (e >= E) return;
    atomicAdd(&d_acc2[ei[E + e]], __ldg(&d_gp[ei[e]]));
}

__global__ void k_sig(const float* __restrict__ b2, float* __restrict__ out, int N) {
    int i = blockIdx.x * blockDim.x + threadIdx.x;
    if (i >= N) return;
    float z = fmaf(d_dinv[i], d_acc2[i], __ldg(&b2[0]));
    out[i] = 1.f / (1.f + __expf(-z));
}

// ---------------- launch (single stream, 6 kernels) ----------------
extern "C" void kernel_launch(void* const* d_in, const int* in_sizes, int n_in,
                              void* d_out, int out_size) {
    const float* x  = (const float*)d_in[0];
    const float* W1 = (const float*)d_in[1];
    const float* b1 = (const float*)d_in[2];
    const float* W2 = (const float*)d_in[3];
    const float* b2 = (const float*)d_in[4];
    const int*   ei = (const int*)d_in[5];

    int N = in_sizes[0] / FIN;     // 100000
    int E = in_sizes[5] / 2;       // 3200000

    const int SMEM_BYTES = (FIN * WPAD + 2 * 256 * XPAD) * (int)sizeof(float);
    static bool inited = false;
    if (!inited) {
        cudaFuncSetAttribute(k_gemmdeg, cudaFuncAttributeMaxDynamicSharedMemorySize,
                             SMEM_BYTES);
        inited = true;
    }

    int nb = (N + 255) / 256;      // 391 blocks
    long long t1 = 2LL * E;

    k_gemmdeg  <<<nb, 384, SMEM_BYTES>>>(x, W1, ei + E, N, E);
    k_scaledinv<<<(N * 4 + 255) / 256, 256>>>(N * 4);
    k_edge1    <<<(unsigned)((t1 + 255) / 256), 256>>>(ei, E);
    k_layer2   <<<(N + 255) / 256, 256>>>(b1, W2, N);
    k_edge2    <<<(E + 255) / 256, 256>>>(ei, E);
    k_sig      <<<(N + 255) / 256, 256>>>(b2, (float*)d_out, N);
}